// round 15
// baseline (speedup 1.0000x reference)
#include <cuda_runtime.h>
#include <cuda_fp16.h>
#include <cstdint>
#include <math.h>

// Problem constants
constexpr int BATCH = 2;
constexpr int SEQ   = 2048;
constexpr int EMB   = 1024;
constexpr int NH    = 16;
constexpr int HD    = 64;
constexpr int HD2   = 32;
constexpr int M_TOT = BATCH * SEQ;   // 4096

// GEMM tiling (mma.sync fp16; A = x (K=1024), B = [Whi | Wlo] (K2=2048)).
constexpr int TM  = 128;
constexpr int TN  = 128;
constexpr int K2  = 2 * EMB;          // 2048
constexpr int KC  = 64;               // fp16 per chunk = 128 B rows
constexpr int NPAIR = 16;             // A chunks
constexpr uint32_t GA_ST = 16384;     // A stage stride (16 KB)
constexpr uint32_t GB_OFF = 32768;    // B region base
constexpr uint32_t GB_ST = 32768;     // B pair-stage stride (2 tiles)
constexpr uint32_t GEMM_SMEM = 98304; // A 2x16K + B 2x32K

// Flash smem layout (bytes): Q 16K | KV ring 3 x 16K (K 8K + V 8K) | l 512B
constexpr uint32_t FQ   = 0;
constexpr uint32_t FKV  = 16384;
constexpr uint32_t FSTG = 16384;
constexpr uint32_t FLSM = 65536;
constexpr uint32_t FLASH_SMEM = 65536 + 512;

// ---------------------------------------------------------------------------
// Scratch (device globals -- no runtime allocation allowed)
// ---------------------------------------------------------------------------
__device__ float g_adapt[BATCH * EMB];

__device__ __half g_xh[(size_t)M_TOT * EMB];        // x rounded to fp16
__device__ __half g_ah[(size_t)M_TOT * EMB];        // attention out fp16
__device__ __half g_w2[4][(size_t)EMB * K2];        // transposed [n][whi | wlo]

__device__ __half g_qh[(size_t)BATCH * NH * SEQ * HD];  // [bh][s][d]
__device__ __half g_kh[(size_t)BATCH * NH * SEQ * HD];
__device__ __half g_vth[(size_t)BATCH * NH * HD * SEQ]; // [bh][d][s]

// ---------------------------------------------------------------------------
// Helpers
// ---------------------------------------------------------------------------
__device__ __forceinline__ uint32_t smem_u32(const void* p) {
    uint32_t a;
    asm("{ .reg .u64 t; cvta.to.shared.u64 t, %1; cvt.u32.u64 %0, t; }" : "=r"(a) : "l"(p));
    return a;
}
#define SWZ128(off) ((off) ^ (((off) >> 3) & 0x70))

__device__ __forceinline__ void cp16(uint32_t d, const void* g) {
    asm volatile("cp.async.cg.shared.global [%0], [%1], 16;" :: "r"(d), "l"(g));
}
__device__ __forceinline__ void ldm4(uint32_t* f, uint32_t addr) {
    asm volatile("ldmatrix.sync.aligned.m8n8.x4.shared.b16 {%0,%1,%2,%3}, [%4];"
        : "=r"(f[0]), "=r"(f[1]), "=r"(f[2]), "=r"(f[3]) : "r"(addr));
}
__device__ __forceinline__ void mma16816(float* c, const uint32_t* a, uint32_t b0, uint32_t b1) {
    asm volatile("mma.sync.aligned.m16n8k16.row.col.f32.f16.f16.f32 "
        "{%0,%1,%2,%3}, {%4,%5,%6,%7}, {%8,%9}, {%0,%1,%2,%3};"
        : "+f"(c[0]), "+f"(c[1]), "+f"(c[2]), "+f"(c[3])
        : "r"(a[0]), "r"(a[1]), "r"(a[2]), "r"(a[3]), "r"(b0), "r"(b1));
}
__device__ __forceinline__ float fast_ex2(float x) {
    float y; asm("ex2.approx.f32 %0, %1;" : "=f"(y) : "f"(x)); return y;
}
__device__ __forceinline__ uint32_t pack_h2(float a, float b) {
    __half2 t = __floats2half2_rn(a, b);
    uint32_t r;
    memcpy(&r, &t, 4);
    return r;
}

// ---------------------------------------------------------------------------
// Kernel: adapt
// ---------------------------------------------------------------------------
__global__ void adapt_kernel(const float* __restrict__ xi,
                             const float* __restrict__ ew1, const float* __restrict__ eb1,
                             const float* __restrict__ lng, const float* __restrict__ lnb,
                             const float* __restrict__ ew2, const float* __restrict__ eb2,
                             const float* __restrict__ gate)
{
    int b = threadIdx.x;
    if (b >= BATCH) return;
    float x[HD2];
    float xv = xi[b];
    float mu = 0.f;
#pragma unroll
    for (int i = 0; i < HD2; ++i) { x[i] = xv * ew1[i] + eb1[i]; mu += x[i]; }
    mu *= (1.0f / HD2);
    float var = 0.f;
#pragma unroll
    for (int i = 0; i < HD2; ++i) { float d = x[i] - mu; var += d * d; }
    var *= (1.0f / HD2);
    float rs = rsqrtf(var + 1e-5f);
#pragma unroll
    for (int i = 0; i < HD2; ++i) {
        float xn = (x[i] - mu) * rs * lng[i] + lnb[i];
        x[i] = 0.5f * xn * (1.f + erff(xn * 0.70710678118654752f));
    }
    float sg[NH];
#pragma unroll
    for (int h = 0; h < NH; ++h) sg[h] = 1.f / (1.f + expf(-gate[h]));
    for (int d = 0; d < HD; ++d) {
        float xe = eb2[d];
#pragma unroll
        for (int i = 0; i < HD2; ++i) xe += x[i] * ew2[i * HD + d];
#pragma unroll
        for (int h = 0; h < NH; ++h)
            g_adapt[b * EMB + h * HD + d] = 1.f + sg[h] * xe;
    }
}

// ---------------------------------------------------------------------------
// Kernel: fp32 -> fp16 (x4 vectorized)
// ---------------------------------------------------------------------------
__global__ void __launch_bounds__(256)
half_kernel(const float4* __restrict__ in, uint2* __restrict__ out, int n4)
{
    int i = blockIdx.x * 256 + threadIdx.x;
    if (i < n4) {
        float4 v = in[i];
        uint2 r;
        r.x = pack_h2(v.x, v.y);
        r.y = pack_h2(v.z, v.w);
        out[i] = r;
    }
}

// ---------------------------------------------------------------------------
// Kernel: all four W[K,N] fp32 -> transposed fp16 [N, 2048] = [hi | lo]
// ---------------------------------------------------------------------------
__global__ void __launch_bounds__(256)
wsplit2_all(const float* __restrict__ Wq, const float* __restrict__ Wk,
            const float* __restrict__ Wv, const float* __restrict__ Wo,
            __half* __restrict__ w2base)
{
    const float* W = (blockIdx.z == 0) ? Wq : (blockIdx.z == 1) ? Wk
                   : (blockIdx.z == 2) ? Wv : Wo;
    __half* out2 = w2base + (size_t)blockIdx.z * EMB * K2;

    __shared__ float t[32][33];
    int n0 = blockIdx.x * 32, k0 = blockIdx.y * 32;
    int tx = threadIdx.x, ty = threadIdx.y;   // (32, 8)
#pragma unroll
    for (int i = 0; i < 32; i += 8)
        t[ty + i][tx] = W[(size_t)(k0 + ty + i) * EMB + n0 + tx];
    __syncthreads();
#pragma unroll
    for (int i = 0; i < 32; i += 8) {
        float x = t[tx][ty + i];              // k=k0+tx, n=n0+ty+i
        __half h = __float2half_rn(x);
        __half l = __float2half_rn(x - __half2float(h));
        size_t base = (size_t)(n0 + ty + i) * K2 + k0 + tx;
        out2[base]       = h;
        out2[base + EMB] = l;
    }
}

// ---------------------------------------------------------------------------
// Kernel: mma.sync fp16 GEMM with paired K-chunks (unchanged from R13).
// ---------------------------------------------------------------------------
__global__ void __launch_bounds__(256)
gemm_mma(const __half* __restrict__ Ah, const __half* __restrict__ w2base,
         const float* __restrict__ bq, const float* __restrict__ bk,
         const float* __restrict__ bv, const float* __restrict__ bo,
         float* __restrict__ out, int mode_base)
{
    extern __shared__ __align__(1024) char smem[];
    const uint32_t sb = smem_u32(smem);
    const int tid  = threadIdx.x;
    const int lane = tid & 31;
    const int wid  = tid >> 5;
    const int wm   = wid >> 1;        // 0..3
    const int wn   = wid & 1;         // 0..1
    const int m0 = blockIdx.y * TM;
    const int n0 = blockIdx.x * TN;
    const int mode = mode_base + blockIdx.z;

    const float* bias = (mode == 0) ? bq : (mode == 1) ? bk : (mode == 2) ? bv : bo;
    const __half* Ab = Ah + (size_t)m0 * EMB;
    const __half* Bb = w2base + (size_t)mode * EMB * K2 + (size_t)n0 * K2;

    float c[2][8][4];
#pragma unroll
    for (int a = 0; a < 2; ++a)
#pragma unroll
        for (int b = 0; b < 8; ++b)
#pragma unroll
            for (int d = 0; d < 4; ++d) c[a][b][d] = 0.f;

#define PREPAIR(p)                                                                     \
    do {                                                                               \
        uint32_t sta = sb + ((p) & 1) * GA_ST;                                         \
        uint32_t stb = sb + GB_OFF + ((p) & 1) * GB_ST;                                \
        _Pragma("unroll")                                                              \
        for (int i = 0; i < 4; ++i) {                                                  \
            int idx = tid + i * 256;                                                   \
            int r = idx >> 3, u = idx & 7;                                             \
            uint32_t sw = SWZ128(r * 128 + u * 16);                                    \
            cp16(sta + sw, Ab + (size_t)r * EMB + (p) * KC + u * 8);                   \
            cp16(stb + sw, Bb + (size_t)r * K2 + (p) * KC + u * 8);                    \
            cp16(stb + 16384 + sw, Bb + (size_t)r * K2 + EMB + (p) * KC + u * 8);      \
        }                                                                              \
        asm volatile("cp.async.commit_group;");                                        \
    } while (0)

    PREPAIR(0);
    asm volatile("cp.async.wait_group 0;");
    __syncthreads();

    for (int p = 0; p < NPAIR; ++p) {
        if (p + 1 < NPAIR) PREPAIR(p + 1);

        const uint32_t sta = sb + (p & 1) * GA_ST;
        const uint32_t stb = sb + GB_OFF + (p & 1) * GB_ST;
        const int rr = lane & 15;

#pragma unroll
        for (int ks = 0; ks < 4; ++ks) {
            const int uu = 2 * ks + (lane >> 4);
            uint32_t afr[2][4];
#pragma unroll
            for (int mt = 0; mt < 2; ++mt)
                ldm4(afr[mt], sta + SWZ128((wm * 32 + mt * 16 + rr) * 128 + uu * 16));
#pragma unroll
            for (int half = 0; half < 2; ++half) {
                uint32_t bfr[4][4];
#pragma unroll
                for (int ng = 0; ng < 4; ++ng)
                    ldm4(bfr[ng], stb + half * 16384 +
                                  SWZ128((wn * 64 + ng * 16 + rr) * 128 + uu * 16));
#pragma unroll
                for (int mt = 0; mt < 2; ++mt)
#pragma unroll
                    for (int ng = 0; ng < 4; ++ng) {
                        mma16816(c[mt][ng * 2],     afr[mt], bfr[ng][0], bfr[ng][2]);
                        mma16816(c[mt][ng * 2 + 1], afr[mt], bfr[ng][1], bfr[ng][3]);
                    }
            }
        }

        if (p + 1 < NPAIR) {
            asm volatile("cp.async.wait_group 0;");
            __syncthreads();
        }
    }
#undef PREPAIR
    __syncthreads();

    // ---------------- epilogues ----------------
    if (mode == 2) {
        // V: stage transposed fp16 in smem, then coalesced store to [bh][d][s]
#pragma unroll
        for (int mt = 0; mt < 2; ++mt) {
            int mrow = wm * 32 + mt * 16 + (lane >> 2);
#pragma unroll
            for (int nt = 0; nt < 8; ++nt) {
                int nl = wn * 64 + nt * 8 + (lane & 3) * 2;
                float b0 = bias[n0 + nl], b1 = bias[n0 + nl + 1];
#pragma unroll
                for (int half = 0; half < 2; ++half) {
                    int ml = mrow + half * 8;
                    *(__half*)(smem + nl * 256 + ml * 2) =
                        __float2half_rn(c[mt][nt][half * 2] + b0);
                    *(__half*)(smem + (nl + 1) * 256 + ml * 2) =
                        __float2half_rn(c[mt][nt][half * 2 + 1] + b1);
                }
            }
        }
        __syncthreads();
        int bq2 = m0 >> 11, sq = m0 & 2047;
        int hbase = n0 >> 6;
        for (int cidx = tid; cidx < 2048; cidx += 256) {
            int nn = cidx >> 4, mc = cidx & 15;
            uint4 hv = *(uint4*)(smem + nn * 256 + mc * 16);
            size_t o = (((size_t)(bq2 * NH + hbase + (nn >> 6)) * HD + (nn & 63)) * SEQ
                        + sq + mc * 8);
            *(uint4*)&g_vth[o] = hv;
        }
        return;
    }

#pragma unroll
    for (int mt = 0; mt < 2; ++mt) {
        int row0 = wm * 32 + mt * 16 + (lane >> 2);
#pragma unroll
        for (int nt = 0; nt < 8; ++nt) {
            int n = n0 + wn * 64 + nt * 8 + (lane & 3) * 2;
            float b0 = bias[n], b1 = bias[n + 1];
#pragma unroll
            for (int half = 0; half < 2; ++half) {
                int m = m0 + row0 + half * 8;
                int b = m >> 11, s = m & 2047;
                float v0 = c[mt][nt][half * 2] + b0;
                float v1 = c[mt][nt][half * 2 + 1] + b1;
                if (mode == 3) {
                    *(float2*)&out[(size_t)m * EMB + n] = make_float2(v0, v1);
                } else {
                    const float sc0 = (mode == 0) ? 0.18033688f : 1.0f;  // 1.442695/8
                    v0 *= g_adapt[b * EMB + n] * sc0;
                    v1 *= g_adapt[b * EMB + n + 1] * sc0;
                    int h = n >> 6, d = n & 63;
                    size_t o = ((size_t)(b * NH + h) * SEQ + s) * HD + d;
                    uint32_t hp = pack_h2(v0, v1);
                    if (mode == 0) *(uint32_t*)&g_qh[o] = hp;
                    else           *(uint32_t*)&g_kh[o] = hp;
                }
            }
        }
    }
}

// ---------------------------------------------------------------------------
// Kernel: tensor-core flash attention, software-pipelined:
// each iteration runs softmax(kb) -> QK(kb+1) -> PV(kb) so the two mma
// streams (QK next / PV current) are independent and hide the softmax wall.
// 3-stage KV ring; KVPRE(kb+2) issued each iteration, wait_group 1 keeps one
// load in flight across a full iteration.
// ---------------------------------------------------------------------------
__global__ void __launch_bounds__(256)
flash_tc()
{
    extern __shared__ __align__(1024) char smem[];
    const uint32_t sb = smem_u32(smem);
    const int tid = threadIdx.x, lane = tid & 31, wid = tid >> 5;
    const int wm = wid >> 1, wn = wid & 1;
    const int s0 = blockIdx.x * 128;
    const int h  = blockIdx.y, b = blockIdx.z;
    const int bh = b * NH + h;
    const int rr = lane & 15;
    const int NKB = SEQ / 64;   // 32

    if (tid < 128) *(float*)(smem + FLSM + tid * 4) = 0.f;

    const __half* qh  = g_qh + ((size_t)bh * SEQ + s0) * HD;
    const __half* kh  = g_kh + (size_t)bh * SEQ * HD;
    const __half* vth = g_vth + (size_t)bh * HD * SEQ;

    // Q tile
#pragma unroll
    for (int i = 0; i < 4; ++i) {
        int idx = tid + i * 256;       // 0..1023
        int r = idx >> 3, u = idx & 7;
        cp16(sb + FQ + SWZ128(r * 128 + u * 16), qh + r * HD + u * 8);
    }
    asm volatile("cp.async.commit_group;");

#define KVPRE(kb)                                                                       \
    do {                                                                                \
        uint32_t st = sb + FKV + ((kb) % 3) * FSTG;                                     \
        _Pragma("unroll")                                                               \
        for (int i = 0; i < 2; ++i) {                                                   \
            int idx = tid + i * 256;     /* 0..511 */                                   \
            int r = idx >> 3, u = idx & 7;                                              \
            uint32_t sw = SWZ128(r * 128 + u * 16);                                     \
            cp16(st + sw,        kh + ((size_t)(kb) * 64 + r) * HD + u * 8);            \
            cp16(st + 8192 + sw, vth + (size_t)r * SEQ + (kb) * 64 + u * 8);            \
        }                                                                               \
        asm volatile("cp.async.commit_group;");                                         \
    } while (0)

// QK for block kb into sc (sc must be zeroed by caller)
#define QK_BLOCK(kb)                                                                    \
    do {                                                                                \
        const uint32_t stg_ = sb + FKV + ((kb) % 3) * FSTG;                             \
        _Pragma("unroll")                                                               \
        for (int ks = 0; ks < 4; ++ks) {                                                \
            const int uu = 2 * ks + (lane >> 4);                                        \
            uint32_t aH[2][4], bH[2][4];                                                \
            _Pragma("unroll")                                                           \
            for (int mt = 0; mt < 2; ++mt)                                              \
                ldm4(aH[mt], sb + FQ + SWZ128((wm * 32 + mt * 16 + rr) * 128 + uu * 16)); \
            _Pragma("unroll")                                                           \
            for (int ng = 0; ng < 2; ++ng)                                              \
                ldm4(bH[ng], stg_ + SWZ128((wn * 32 + ng * 16 + rr) * 128 + uu * 16));  \
            _Pragma("unroll")                                                           \
            for (int mt = 0; mt < 2; ++mt)                                              \
                _Pragma("unroll")                                                       \
                for (int ng = 0; ng < 2; ++ng) {                                        \
                    mma16816(sc[mt][ng * 2],     aH[mt], bH[ng][0], bH[ng][2]);         \
                    mma16816(sc[mt][ng * 2 + 1], aH[mt], bH[ng][1], bH[ng][3]);         \
                }                                                                       \
        }                                                                               \
    } while (0)

    KVPRE(0);
    KVPRE(1);
    // outstanding groups: {Q, KV0, KV1}; wait until <=1 left => Q and KV0 done
    asm volatile("cp.async.wait_group 1;");
    __syncthreads();

    float oc[2][8][4];
#pragma unroll
    for (int a = 0; a < 2; ++a)
#pragma unroll
        for (int f = 0; f < 8; ++f)
#pragma unroll
            for (int d = 0; d < 4; ++d) oc[a][f][d] = 0.f;
    float l_part[4] = {0.f, 0.f, 0.f, 0.f};

    float sc[2][4][4];
#pragma unroll
    for (int a = 0; a < 2; ++a)
#pragma unroll
        for (int f = 0; f < 4; ++f)
#pragma unroll
            for (int d = 0; d < 4; ++d) sc[a][f][d] = 0.f;
    QK_BLOCK(0);

#pragma unroll 1
    for (int kb = 0; kb < NKB; ++kb) {
        // protect stage (kb+2)%3 == (kb-1)%3 from last iter's PV readers
        if (kb + 2 < NKB) {
            __syncthreads();
            KVPRE(kb + 2);
        }

        // ---- softmax(kb): sc -> pA/pB (sc dead after) ----
        uint32_t pA[2][4], pB[2][4];
#pragma unroll
        for (int mt = 0; mt < 2; ++mt)
#pragma unroll
            for (int nf = 0; nf < 4; ++nf) {
                float p0 = fast_ex2(sc[mt][nf][0]);
                float p1 = fast_ex2(sc[mt][nf][1]);
                float p2 = fast_ex2(sc[mt][nf][2]);
                float p3 = fast_ex2(sc[mt][nf][3]);
                l_part[mt * 2 + 0] += p0 + p1;
                l_part[mt * 2 + 1] += p2 + p3;
                pA[mt][nf] = pack_h2(p0, p1);
                pB[mt][nf] = pack_h2(p2, p3);
            }

        // ---- QK(kb+1) into freshly-zeroed sc (independent of PV below) ----
        if (kb + 1 < NKB) {
            if (kb + 2 < NKB)
                asm volatile("cp.async.wait_group 1;");   // kb+1 resident
            else
                asm volatile("cp.async.wait_group 0;");
            __syncthreads();
#pragma unroll
            for (int a = 0; a < 2; ++a)
#pragma unroll
                for (int f = 0; f < 4; ++f)
#pragma unroll
                    for (int d = 0; d < 4; ++d) sc[a][f][d] = 0.f;
            QK_BLOCK(kb + 1);
        }

        // ---- PV(kb): O_partial += P V over this warp's 32 keys, all 64 d ----
        {
            const uint32_t stg = sb + FKV + (kb % 3) * FSTG;
#pragma unroll
            for (int ksp = 0; ksp < 2; ++ksp) {
                const int uu = 2 * (wn * 2 + ksp) + (lane >> 4);
                uint32_t bV[4][4];
#pragma unroll
                for (int g = 0; g < 4; ++g)
                    ldm4(bV[g], stg + 8192 + SWZ128((g * 16 + rr) * 128 + uu * 16));
#pragma unroll
                for (int mt = 0; mt < 2; ++mt) {
                    uint32_t aP[4] = {pA[mt][2 * ksp], pB[mt][2 * ksp],
                                      pA[mt][2 * ksp + 1], pB[mt][2 * ksp + 1]};
#pragma unroll
                    for (int g = 0; g < 4; ++g) {
                        mma16816(oc[mt][2 * g],     aP, bV[g][0], bV[g][2]);
                        mma16816(oc[mt][2 * g + 1], aP, bV[g][1], bV[g][3]);
                    }
                }
            }
        }
    }
#undef KVPRE
#undef QK_BLOCK

    // ---- reduce l across the 4 lanes of each row-group ----
#pragma unroll
    for (int j = 0; j < 4; ++j) {
        l_part[j] += __shfl_xor_sync(0xFFFFFFFF, l_part[j], 1);
        l_part[j] += __shfl_xor_sync(0xFFFFFFFF, l_part[j], 2);
    }
    if ((lane & 3) == 0) {
#pragma unroll
        for (int mt = 0; mt < 2; ++mt)
#pragma unroll
            for (int half = 0; half < 2; ++half) {
                int r = wm * 32 + mt * 16 + (lane >> 2) + half * 8;
                atomicAdd((float*)(smem + FLSM + r * 4), l_part[mt * 2 + half]);
            }
    }
    __syncthreads();   // all PV done; Q area now dead -> O reduce buffer (32 KB)

    if (wn == 1) {
#pragma unroll
        for (int mt = 0; mt < 2; ++mt) {
            int row = wm * 32 + mt * 16 + (lane >> 2);
#pragma unroll
            for (int nf = 0; nf < 8; ++nf) {
                int col = nf * 8 + (lane & 3) * 2;
                *(float2*)(smem + (row * 64 + col) * 4) =
                    make_float2(oc[mt][nf][0], oc[mt][nf][1]);
                *(float2*)(smem + ((row + 8) * 64 + col) * 4) =
                    make_float2(oc[mt][nf][2], oc[mt][nf][3]);
            }
        }
    }
    __syncthreads();

    if (wn == 0) {
#pragma unroll
        for (int mt = 0; mt < 2; ++mt)
#pragma unroll
            for (int half = 0; half < 2; ++half) {
                int r = wm * 32 + mt * 16 + (lane >> 2) + half * 8;
                float inv = 1.f / *(float*)(smem + FLSM + r * 4);
                size_t mrow = (size_t)(b * SEQ + s0 + r) * EMB;
#pragma unroll
                for (int nf = 0; nf < 8; ++nf) {
                    int col = nf * 8 + (lane & 3) * 2;
                    float2 part = *(float2*)(smem + (r * 64 + col) * 4);
                    float v0 = (oc[mt][nf][half * 2]     + part.x) * inv;
                    float v1 = (oc[mt][nf][half * 2 + 1] + part.y) * inv;
                    *(uint32_t*)&g_ah[mrow + h * HD + col] = pack_h2(v0, v1);
                }
            }
    }
}

// ---------------------------------------------------------------------------
// Launch
// ---------------------------------------------------------------------------
extern "C" void kernel_launch(void* const* d_in, const int* in_sizes, int n_in,
                              void* d_out, int out_size)
{
    const float* query = (const float*)d_in[0];
    const float* xi    = (const float*)d_in[1];
    const float* Wq    = (const float*)d_in[2];
    const float* bq    = (const float*)d_in[3];
    const float* Wk    = (const float*)d_in[4];
    const float* bk    = (const float*)d_in[5];
    const float* Wv    = (const float*)d_in[6];
    const float* bv    = (const float*)d_in[7];
    const float* Wo    = (const float*)d_in[8];
    const float* bo    = (const float*)d_in[9];
    const float* ew1   = (const float*)d_in[10];
    const float* eb1   = (const float*)d_in[11];
    const float* lng   = (const float*)d_in[12];
    const float* lnb   = (const float*)d_in[13];
    const float* ew2   = (const float*)d_in[14];
    const float* eb2   = (const float*)d_in[15];
    const float* gate  = (const float*)d_in[16];
    float* out = (float*)d_out;

    // Idempotent, capture-safe, no static guard (harness rule).
    cudaFuncSetAttribute(gemm_mma, cudaFuncAttributeMaxDynamicSharedMemorySize, GEMM_SMEM);
    cudaFuncSetAttribute(flash_tc, cudaFuncAttributeMaxDynamicSharedMemorySize, FLASH_SMEM);

    int nX = M_TOT * EMB;
    __half *xh, *ah, *w2;
    cudaGetSymbolAddress((void**)&xh, g_xh);
    cudaGetSymbolAddress((void**)&ah, g_ah);
    cudaGetSymbolAddress((void**)&w2, g_w2);

    dim3 wgrid(EMB / 32, EMB / 32, 4);
    dim3 wblk(32, 8);
    dim3 gq(EMB / TN, M_TOT / TM, 3);    // QKV fused
    dim3 go(EMB / TN, M_TOT / TM, 1);    // O

    adapt_kernel<<<1, 32>>>(xi, ew1, eb1, lng, lnb, ew2, eb2, gate);
    half_kernel<<<nX / 1024, 256>>>((const float4*)query, (uint2*)xh, nX / 4);
    wsplit2_all<<<wgrid, wblk>>>(Wq, Wk, Wv, Wo, w2);
    gemm_mma<<<gq, 256, GEMM_SMEM>>>(xh, w2, bq, bk, bv, bo, out, 0);
    flash_tc<<<dim3(SEQ / 128, NH, BATCH), 256, FLASH_SMEM>>>();
    gemm_mma<<<go, 256, GEMM_SMEM>>>(ah, w2, bq, bk, bv, bo, out, 3);
}

// round 16
// speedup vs baseline: 1.0944x; 1.0944x over previous
#include <cuda_runtime.h>
#include <cuda_fp16.h>
#include <cstdint>
#include <math.h>

// Problem constants
constexpr int BATCH = 2;
constexpr int SEQ   = 2048;
constexpr int EMB   = 1024;
constexpr int NH    = 16;
constexpr int HD    = 64;
constexpr int HD2   = 32;
constexpr int M_TOT = BATCH * SEQ;   // 4096

// GEMM tiling (mma.sync fp16; A = x (K=1024), B = [Whi | Wlo] (K2=2048)).
constexpr int TM  = 128;
constexpr int TN  = 128;
constexpr int K2  = 2 * EMB;          // 2048
constexpr int KC  = 64;               // fp16 per chunk = 128 B rows
constexpr int NPAIR = 16;             // A chunks
constexpr uint32_t GA_ST = 16384;     // A stage stride (16 KB)
constexpr uint32_t GB_OFF = 32768;    // B region base
constexpr uint32_t GB_ST = 32768;     // B pair-stage stride (2 tiles)
constexpr uint32_t GEMM_SMEM = 98304; // A 2x16K + B 2x32K

// Flash smem layout (bytes): Q 16K | KV 2 stages x 32K (2 sub-blocks each:
// K 8K + V 8K) | l 512B.  80.5 KB total -> 2 CTAs/SM.
constexpr uint32_t FQ   = 0;
constexpr uint32_t FKV  = 16384;
constexpr uint32_t FSTG = 32768;       // stage stride (2 sub-blocks)
constexpr uint32_t FSUB = 16384;       // sub-block stride (K 8K + V 8K)
constexpr uint32_t FLSM = 81920;
constexpr uint32_t FLASH_SMEM = 81920 + 512;

// ---------------------------------------------------------------------------
// Scratch (device globals -- no runtime allocation allowed)
// ---------------------------------------------------------------------------
__device__ float g_adapt[BATCH * EMB];

__device__ __half g_xh[(size_t)M_TOT * EMB];        // x rounded to fp16
__device__ __half g_ah[(size_t)M_TOT * EMB];        // attention out fp16
__device__ __half g_w2[4][(size_t)EMB * K2];        // transposed [n][whi | wlo]

__device__ __half g_qh[(size_t)BATCH * NH * SEQ * HD];  // [bh][s][d]
__device__ __half g_kh[(size_t)BATCH * NH * SEQ * HD];
__device__ __half g_vth[(size_t)BATCH * NH * HD * SEQ]; // [bh][d][s]

// ---------------------------------------------------------------------------
// Helpers
// ---------------------------------------------------------------------------
__device__ __forceinline__ uint32_t smem_u32(const void* p) {
    uint32_t a;
    asm("{ .reg .u64 t; cvta.to.shared.u64 t, %1; cvt.u32.u64 %0, t; }" : "=r"(a) : "l"(p));
    return a;
}
#define SWZ128(off) ((off) ^ (((off) >> 3) & 0x70))

__device__ __forceinline__ void cp16(uint32_t d, const void* g) {
    asm volatile("cp.async.cg.shared.global [%0], [%1], 16;" :: "r"(d), "l"(g));
}
__device__ __forceinline__ void ldm4(uint32_t* f, uint32_t addr) {
    asm volatile("ldmatrix.sync.aligned.m8n8.x4.shared.b16 {%0,%1,%2,%3}, [%4];"
        : "=r"(f[0]), "=r"(f[1]), "=r"(f[2]), "=r"(f[3]) : "r"(addr));
}
__device__ __forceinline__ void mma16816(float* c, const uint32_t* a, uint32_t b0, uint32_t b1) {
    asm volatile("mma.sync.aligned.m16n8k16.row.col.f32.f16.f16.f32 "
        "{%0,%1,%2,%3}, {%4,%5,%6,%7}, {%8,%9}, {%0,%1,%2,%3};"
        : "+f"(c[0]), "+f"(c[1]), "+f"(c[2]), "+f"(c[3])
        : "r"(a[0]), "r"(a[1]), "r"(a[2]), "r"(a[3]), "r"(b0), "r"(b1));
}
__device__ __forceinline__ float fast_ex2(float x) {
    float y; asm("ex2.approx.f32 %0, %1;" : "=f"(y) : "f"(x)); return y;
}
__device__ __forceinline__ uint32_t pack_h2(float a, float b) {
    __half2 t = __floats2half2_rn(a, b);
    uint32_t r;
    memcpy(&r, &t, 4);
    return r;
}

// ---------------------------------------------------------------------------
// Kernel: adapt
// ---------------------------------------------------------------------------
__global__ void adapt_kernel(const float* __restrict__ xi,
                             const float* __restrict__ ew1, const float* __restrict__ eb1,
                             const float* __restrict__ lng, const float* __restrict__ lnb,
                             const float* __restrict__ ew2, const float* __restrict__ eb2,
                             const float* __restrict__ gate)
{
    int b = threadIdx.x;
    if (b >= BATCH) return;
    float x[HD2];
    float xv = xi[b];
    float mu = 0.f;
#pragma unroll
    for (int i = 0; i < HD2; ++i) { x[i] = xv * ew1[i] + eb1[i]; mu += x[i]; }
    mu *= (1.0f / HD2);
    float var = 0.f;
#pragma unroll
    for (int i = 0; i < HD2; ++i) { float d = x[i] - mu; var += d * d; }
    var *= (1.0f / HD2);
    float rs = rsqrtf(var + 1e-5f);
#pragma unroll
    for (int i = 0; i < HD2; ++i) {
        float xn = (x[i] - mu) * rs * lng[i] + lnb[i];
        x[i] = 0.5f * xn * (1.f + erff(xn * 0.70710678118654752f));
    }
    float sg[NH];
#pragma unroll
    for (int h = 0; h < NH; ++h) sg[h] = 1.f / (1.f + expf(-gate[h]));
    for (int d = 0; d < HD; ++d) {
        float xe = eb2[d];
#pragma unroll
        for (int i = 0; i < HD2; ++i) xe += x[i] * ew2[i * HD + d];
#pragma unroll
        for (int h = 0; h < NH; ++h)
            g_adapt[b * EMB + h * HD + d] = 1.f + sg[h] * xe;
    }
}

// ---------------------------------------------------------------------------
// Kernel: fp32 -> fp16 (x4 vectorized)
// ---------------------------------------------------------------------------
__global__ void __launch_bounds__(256)
half_kernel(const float4* __restrict__ in, uint2* __restrict__ out, int n4)
{
    int i = blockIdx.x * 256 + threadIdx.x;
    if (i < n4) {
        float4 v = in[i];
        uint2 r;
        r.x = pack_h2(v.x, v.y);
        r.y = pack_h2(v.z, v.w);
        out[i] = r;
    }
}

// ---------------------------------------------------------------------------
// Kernel: all four W[K,N] fp32 -> transposed fp16 [N, 2048] = [hi | lo]
// ---------------------------------------------------------------------------
__global__ void __launch_bounds__(256)
wsplit2_all(const float* __restrict__ Wq, const float* __restrict__ Wk,
            const float* __restrict__ Wv, const float* __restrict__ Wo,
            __half* __restrict__ w2base)
{
    const float* W = (blockIdx.z == 0) ? Wq : (blockIdx.z == 1) ? Wk
                   : (blockIdx.z == 2) ? Wv : Wo;
    __half* out2 = w2base + (size_t)blockIdx.z * EMB * K2;

    __shared__ float t[32][33];
    int n0 = blockIdx.x * 32, k0 = blockIdx.y * 32;
    int tx = threadIdx.x, ty = threadIdx.y;   // (32, 8)
#pragma unroll
    for (int i = 0; i < 32; i += 8)
        t[ty + i][tx] = W[(size_t)(k0 + ty + i) * EMB + n0 + tx];
    __syncthreads();
#pragma unroll
    for (int i = 0; i < 32; i += 8) {
        float x = t[tx][ty + i];              // k=k0+tx, n=n0+ty+i
        __half h = __float2half_rn(x);
        __half l = __float2half_rn(x - __half2float(h));
        size_t base = (size_t)(n0 + ty + i) * K2 + k0 + tx;
        out2[base]       = h;
        out2[base + EMB] = l;
    }
}

// ---------------------------------------------------------------------------
// Kernel: mma.sync fp16 GEMM with paired K-chunks (unchanged from R13).
// ---------------------------------------------------------------------------
__global__ void __launch_bounds__(256)
gemm_mma(const __half* __restrict__ Ah, const __half* __restrict__ w2base,
         const float* __restrict__ bq, const float* __restrict__ bk,
         const float* __restrict__ bv, const float* __restrict__ bo,
         float* __restrict__ out, int mode_base)
{
    extern __shared__ __align__(1024) char smem[];
    const uint32_t sb = smem_u32(smem);
    const int tid  = threadIdx.x;
    const int lane = tid & 31;
    const int wid  = tid >> 5;
    const int wm   = wid >> 1;        // 0..3
    const int wn   = wid & 1;         // 0..1
    const int m0 = blockIdx.y * TM;
    const int n0 = blockIdx.x * TN;
    const int mode = mode_base + blockIdx.z;

    const float* bias = (mode == 0) ? bq : (mode == 1) ? bk : (mode == 2) ? bv : bo;
    const __half* Ab = Ah + (size_t)m0 * EMB;
    const __half* Bb = w2base + (size_t)mode * EMB * K2 + (size_t)n0 * K2;

    float c[2][8][4];
#pragma unroll
    for (int a = 0; a < 2; ++a)
#pragma unroll
        for (int b = 0; b < 8; ++b)
#pragma unroll
            for (int d = 0; d < 4; ++d) c[a][b][d] = 0.f;

#define PREPAIR(p)                                                                     \
    do {                                                                               \
        uint32_t sta = sb + ((p) & 1) * GA_ST;                                         \
        uint32_t stb = sb + GB_OFF + ((p) & 1) * GB_ST;                                \
        _Pragma("unroll")                                                              \
        for (int i = 0; i < 4; ++i) {                                                  \
            int idx = tid + i * 256;                                                   \
            int r = idx >> 3, u = idx & 7;                                             \
            uint32_t sw = SWZ128(r * 128 + u * 16);                                    \
            cp16(sta + sw, Ab + (size_t)r * EMB + (p) * KC + u * 8);                   \
            cp16(stb + sw, Bb + (size_t)r * K2 + (p) * KC + u * 8);                    \
            cp16(stb + 16384 + sw, Bb + (size_t)r * K2 + EMB + (p) * KC + u * 8);      \
        }                                                                              \
        asm volatile("cp.async.commit_group;");                                        \
    } while (0)

    PREPAIR(0);
    asm volatile("cp.async.wait_group 0;");
    __syncthreads();

    for (int p = 0; p < NPAIR; ++p) {
        if (p + 1 < NPAIR) PREPAIR(p + 1);

        const uint32_t sta = sb + (p & 1) * GA_ST;
        const uint32_t stb = sb + GB_OFF + (p & 1) * GB_ST;
        const int rr = lane & 15;

#pragma unroll
        for (int ks = 0; ks < 4; ++ks) {
            const int uu = 2 * ks + (lane >> 4);
            uint32_t afr[2][4];
#pragma unroll
            for (int mt = 0; mt < 2; ++mt)
                ldm4(afr[mt], sta + SWZ128((wm * 32 + mt * 16 + rr) * 128 + uu * 16));
#pragma unroll
            for (int half = 0; half < 2; ++half) {
                uint32_t bfr[4][4];
#pragma unroll
                for (int ng = 0; ng < 4; ++ng)
                    ldm4(bfr[ng], stb + half * 16384 +
                                  SWZ128((wn * 64 + ng * 16 + rr) * 128 + uu * 16));
#pragma unroll
                for (int mt = 0; mt < 2; ++mt)
#pragma unroll
                    for (int ng = 0; ng < 4; ++ng) {
                        mma16816(c[mt][ng * 2],     afr[mt], bfr[ng][0], bfr[ng][2]);
                        mma16816(c[mt][ng * 2 + 1], afr[mt], bfr[ng][1], bfr[ng][3]);
                    }
            }
        }

        if (p + 1 < NPAIR) {
            asm volatile("cp.async.wait_group 0;");
            __syncthreads();
        }
    }
#undef PREPAIR
    __syncthreads();

    // ---------------- epilogues ----------------
    if (mode == 2) {
        // V: stage transposed fp16 in smem, then coalesced store to [bh][d][s]
#pragma unroll
        for (int mt = 0; mt < 2; ++mt) {
            int mrow = wm * 32 + mt * 16 + (lane >> 2);
#pragma unroll
            for (int nt = 0; nt < 8; ++nt) {
                int nl = wn * 64 + nt * 8 + (lane & 3) * 2;
                float b0 = bias[n0 + nl], b1 = bias[n0 + nl + 1];
#pragma unroll
                for (int half = 0; half < 2; ++half) {
                    int ml = mrow + half * 8;
                    *(__half*)(smem + nl * 256 + ml * 2) =
                        __float2half_rn(c[mt][nt][half * 2] + b0);
                    *(__half*)(smem + (nl + 1) * 256 + ml * 2) =
                        __float2half_rn(c[mt][nt][half * 2 + 1] + b1);
                }
            }
        }
        __syncthreads();
        int bq2 = m0 >> 11, sq = m0 & 2047;
        int hbase = n0 >> 6;
        for (int cidx = tid; cidx < 2048; cidx += 256) {
            int nn = cidx >> 4, mc = cidx & 15;
            uint4 hv = *(uint4*)(smem + nn * 256 + mc * 16);
            size_t o = (((size_t)(bq2 * NH + hbase + (nn >> 6)) * HD + (nn & 63)) * SEQ
                        + sq + mc * 8);
            *(uint4*)&g_vth[o] = hv;
        }
        return;
    }

#pragma unroll
    for (int mt = 0; mt < 2; ++mt) {
        int row0 = wm * 32 + mt * 16 + (lane >> 2);
#pragma unroll
        for (int nt = 0; nt < 8; ++nt) {
            int n = n0 + wn * 64 + nt * 8 + (lane & 3) * 2;
            float b0 = bias[n], b1 = bias[n + 1];
#pragma unroll
            for (int half = 0; half < 2; ++half) {
                int m = m0 + row0 + half * 8;
                int b = m >> 11, s = m & 2047;
                float v0 = c[mt][nt][half * 2] + b0;
                float v1 = c[mt][nt][half * 2 + 1] + b1;
                if (mode == 3) {
                    *(float2*)&out[(size_t)m * EMB + n] = make_float2(v0, v1);
                } else {
                    const float sc0 = (mode == 0) ? 0.18033688f : 1.0f;  // 1.442695/8
                    v0 *= g_adapt[b * EMB + n] * sc0;
                    v1 *= g_adapt[b * EMB + n + 1] * sc0;
                    int h = n >> 6, d = n & 63;
                    size_t o = ((size_t)(b * NH + h) * SEQ + s) * HD + d;
                    uint32_t hp = pack_h2(v0, v1);
                    if (mode == 0) *(uint32_t*)&g_qh[o] = hp;
                    else           *(uint32_t*)&g_kh[o] = hp;
                }
            }
        }
    }
}

// ---------------------------------------------------------------------------
// Kernel: tensor-core flash attention (R14 structure, 2 CTAs/SM) with TWO
// 64-key sub-blocks per pipeline stage: half the barrier walls, identical
// registers and numerics (same op order as R14).
// ---------------------------------------------------------------------------
__global__ void __launch_bounds__(256, 2)
flash_tc()
{
    extern __shared__ __align__(1024) char smem[];
    const uint32_t sb = smem_u32(smem);
    const int tid = threadIdx.x, lane = tid & 31, wid = tid >> 5;
    const int wm = wid >> 1, wn = wid & 1;
    const int s0 = blockIdx.x * 128;
    const int h  = blockIdx.y, b = blockIdx.z;
    const int bh = b * NH + h;
    const int rr = lane & 15;
    const int NST = SEQ / 128;    // 16 stages, 2 sub-blocks each

    if (tid < 128) *(float*)(smem + FLSM + tid * 4) = 0.f;

    const __half* qh  = g_qh + ((size_t)bh * SEQ + s0) * HD;
    const __half* kh  = g_kh + (size_t)bh * SEQ * HD;
    const __half* vth = g_vth + (size_t)bh * HD * SEQ;

    // Q tile
#pragma unroll
    for (int i = 0; i < 4; ++i) {
        int idx = tid + i * 256;       // 0..1023
        int r = idx >> 3, u = idx & 7;
        cp16(sb + FQ + SWZ128(r * 128 + u * 16), qh + r * HD + u * 8);
    }
    asm volatile("cp.async.commit_group;");

// load stage st (key blocks 2*st and 2*st+1, 32 KB)
#define KVPRE(st)                                                                       \
    do {                                                                                \
        uint32_t base_ = sb + FKV + ((st) & 1) * FSTG;                                  \
        _Pragma("unroll")                                                               \
        for (int sub_ = 0; sub_ < 2; ++sub_) {                                          \
            int kb_ = (st) * 2 + sub_;                                                  \
            uint32_t stg_ = base_ + sub_ * FSUB;                                        \
            _Pragma("unroll")                                                           \
            for (int i = 0; i < 2; ++i) {                                               \
                int idx = tid + i * 256;     /* 0..511 */                               \
                int r = idx >> 3, u = idx & 7;                                          \
                uint32_t sw = SWZ128(r * 128 + u * 16);                                 \
                cp16(stg_ + sw,        kh + ((size_t)kb_ * 64 + r) * HD + u * 8);       \
                cp16(stg_ + 8192 + sw, vth + (size_t)r * SEQ + kb_ * 64 + u * 8);       \
            }                                                                           \
        }                                                                               \
        asm volatile("cp.async.commit_group;");                                         \
    } while (0)

    KVPRE(0);
    asm volatile("cp.async.wait_group 0;");
    __syncthreads();

    float oc[2][8][4];
#pragma unroll
    for (int a = 0; a < 2; ++a)
#pragma unroll
        for (int f = 0; f < 8; ++f)
#pragma unroll
            for (int d = 0; d < 4; ++d) oc[a][f][d] = 0.f;
    float l_part[4] = {0.f, 0.f, 0.f, 0.f};

#pragma unroll 1
    for (int st = 0; st < NST; ++st) {
        if (st + 1 < NST) KVPRE(st + 1);

#pragma unroll 1
        for (int sub = 0; sub < 2; ++sub) {
            const uint32_t stg = sb + FKV + (st & 1) * FSTG + sub * FSUB;

            // ---- S = Q K^T (fp16 single term) ----
            float sc[2][4][4];
#pragma unroll
            for (int a = 0; a < 2; ++a)
#pragma unroll
                for (int f = 0; f < 4; ++f)
#pragma unroll
                    for (int d = 0; d < 4; ++d) sc[a][f][d] = 0.f;

#pragma unroll
            for (int ks = 0; ks < 4; ++ks) {
                const int uu = 2 * ks + (lane >> 4);
                uint32_t aH[2][4], bH[2][4];
#pragma unroll
                for (int mt = 0; mt < 2; ++mt)
                    ldm4(aH[mt], sb + FQ + SWZ128((wm * 32 + mt * 16 + rr) * 128 + uu * 16));
#pragma unroll
                for (int ng = 0; ng < 2; ++ng)
                    ldm4(bH[ng], stg + SWZ128((wn * 32 + ng * 16 + rr) * 128 + uu * 16));
#pragma unroll
                for (int mt = 0; mt < 2; ++mt)
#pragma unroll
                    for (int ng = 0; ng < 2; ++ng) {
                        mma16816(sc[mt][ng * 2],     aH[mt], bH[ng][0], bH[ng][2]);
                        mma16816(sc[mt][ng * 2 + 1], aH[mt], bH[ng][1], bH[ng][3]);
                    }
            }

            // ---- p = 2^s; pack fp16 A-fragments in registers ----
            uint32_t pA[2][4], pB[2][4];
#pragma unroll
            for (int mt = 0; mt < 2; ++mt)
#pragma unroll
                for (int nf = 0; nf < 4; ++nf) {
                    float p0 = fast_ex2(sc[mt][nf][0]);
                    float p1 = fast_ex2(sc[mt][nf][1]);
                    float p2 = fast_ex2(sc[mt][nf][2]);
                    float p3 = fast_ex2(sc[mt][nf][3]);
                    l_part[mt * 2 + 0] += p0 + p1;
                    l_part[mt * 2 + 1] += p2 + p3;
                    pA[mt][nf] = pack_h2(p0, p1);
                    pB[mt][nf] = pack_h2(p2, p3);
                }

            // ---- O_partial += P V over this warp's 32 keys, all 64 d ----
#pragma unroll
            for (int ksp = 0; ksp < 2; ++ksp) {
                const int uu = 2 * (wn * 2 + ksp) + (lane >> 4);
                uint32_t bV[4][4];
#pragma unroll
                for (int g = 0; g < 4; ++g)
                    ldm4(bV[g], stg + 8192 + SWZ128((g * 16 + rr) * 128 + uu * 16));
#pragma unroll
                for (int mt = 0; mt < 2; ++mt) {
                    uint32_t aP[4] = {pA[mt][2 * ksp], pB[mt][2 * ksp],
                                      pA[mt][2 * ksp + 1], pB[mt][2 * ksp + 1]};
#pragma unroll
                    for (int g = 0; g < 4; ++g) {
                        mma16816(oc[mt][2 * g],     aP, bV[g][0], bV[g][2]);
                        mma16816(oc[mt][2 * g + 1], aP, bV[g][1], bV[g][3]);
                    }
                }
            }
        }

        // stage st fully consumed; wait for st+1 data and make write-safe
        if (st + 1 < NST) {
            asm volatile("cp.async.wait_group 0;");
            __syncthreads();
        }
    }
#undef KVPRE

    // ---- reduce l across the 4 lanes of each row-group ----
#pragma unroll
    for (int j = 0; j < 4; ++j) {
        l_part[j] += __shfl_xor_sync(0xFFFFFFFF, l_part[j], 1);
        l_part[j] += __shfl_xor_sync(0xFFFFFFFF, l_part[j], 2);
    }
    if ((lane & 3) == 0) {
#pragma unroll
        for (int mt = 0; mt < 2; ++mt)
#pragma unroll
            for (int half = 0; half < 2; ++half) {
                int r = wm * 32 + mt * 16 + (lane >> 2) + half * 8;
                atomicAdd((float*)(smem + FLSM + r * 4), l_part[mt * 2 + half]);
            }
    }
    __syncthreads();   // all PV done; Q area now dead -> O reduce buffer (32 KB)

    if (wn == 1) {
#pragma unroll
        for (int mt = 0; mt < 2; ++mt) {
            int row = wm * 32 + mt * 16 + (lane >> 2);
#pragma unroll
            for (int nf = 0; nf < 8; ++nf) {
                int col = nf * 8 + (lane & 3) * 2;
                *(float2*)(smem + (row * 64 + col) * 4) =
                    make_float2(oc[mt][nf][0], oc[mt][nf][1]);
                *(float2*)(smem + ((row + 8) * 64 + col) * 4) =
                    make_float2(oc[mt][nf][2], oc[mt][nf][3]);
            }
        }
    }
    __syncthreads();

    if (wn == 0) {
#pragma unroll
        for (int mt = 0; mt < 2; ++mt)
#pragma unroll
            for (int half = 0; half < 2; ++half) {
                int r = wm * 32 + mt * 16 + (lane >> 2) + half * 8;
                float inv = 1.f / *(float*)(smem + FLSM + r * 4);
                size_t mrow = (size_t)(b * SEQ + s0 + r) * EMB;
#pragma unroll
                for (int nf = 0; nf < 8; ++nf) {
                    int col = nf * 8 + (lane & 3) * 2;
                    float2 part = *(float2*)(smem + (r * 64 + col) * 4);
                    float v0 = (oc[mt][nf][half * 2]     + part.x) * inv;
                    float v1 = (oc[mt][nf][half * 2 + 1] + part.y) * inv;
                    *(uint32_t*)&g_ah[mrow + h * HD + col] = pack_h2(v0, v1);
                }
            }
    }
}

// ---------------------------------------------------------------------------
// Launch
// ---------------------------------------------------------------------------
extern "C" void kernel_launch(void* const* d_in, const int* in_sizes, int n_in,
                              void* d_out, int out_size)
{
    const float* query = (const float*)d_in[0];
    const float* xi    = (const float*)d_in[1];
    const float* Wq    = (const float*)d_in[2];
    const float* bq    = (const float*)d_in[3];
    const float* Wk    = (const float*)d_in[4];
    const float* bk    = (const float*)d_in[5];
    const float* Wv    = (const float*)d_in[6];
    const float* bv    = (const float*)d_in[7];
    const float* Wo    = (const float*)d_in[8];
    const float* bo    = (const float*)d_in[9];
    const float* ew1   = (const float*)d_in[10];
    const float* eb1   = (const float*)d_in[11];
    const float* lng   = (const float*)d_in[12];
    const float* lnb   = (const float*)d_in[13];
    const float* ew2   = (const float*)d_in[14];
    const float* eb2   = (const float*)d_in[15];
    const float* gate  = (const float*)d_in[16];
    float* out = (float*)d_out;

    // Idempotent, capture-safe, no static guard (harness rule).
    cudaFuncSetAttribute(gemm_mma, cudaFuncAttributeMaxDynamicSharedMemorySize, GEMM_SMEM);
    cudaFuncSetAttribute(flash_tc, cudaFuncAttributeMaxDynamicSharedMemorySize, FLASH_SMEM);

    int nX = M_TOT * EMB;
    __half *xh, *ah, *w2;
    cudaGetSymbolAddress((void**)&xh, g_xh);
    cudaGetSymbolAddress((void**)&ah, g_ah);
    cudaGetSymbolAddress((void**)&w2, g_w2);

    dim3 wgrid(EMB / 32, EMB / 32, 4);
    dim3 wblk(32, 8);
    dim3 gq(EMB / TN, M_TOT / TM, 3);    // QKV fused
    dim3 go(EMB / TN, M_TOT / TM, 1);    // O

    adapt_kernel<<<1, 32>>>(xi, ew1, eb1, lng, lnb, ew2, eb2, gate);
    half_kernel<<<nX / 1024, 256>>>((const float4*)query, (uint2*)xh, nX / 4);
    wsplit2_all<<<wgrid, wblk>>>(Wq, Wk, Wv, Wo, w2);
    gemm_mma<<<gq, 256, GEMM_SMEM>>>(xh, w2, bq, bk, bv, bo, out, 0);
    flash_tc<<<dim3(SEQ / 128, NH, BATCH), 256, FLASH_SMEM>>>();
    gemm_mma<<<go, 256, GEMM_SMEM>>>(ah, w2, bq, bk, bv, bo, out, 3);
}

// round 17
// speedup vs baseline: 1.2859x; 1.1750x over previous
#include <cuda_runtime.h>
#include <cuda_fp16.h>
#include <cstdint>
#include <math.h>

// Problem constants
constexpr int BATCH = 2;
constexpr int SEQ   = 2048;
constexpr int EMB   = 1024;
constexpr int NH    = 16;
constexpr int HD    = 64;
constexpr int HD2   = 32;
constexpr int M_TOT = BATCH * SEQ;   // 4096

// GEMM tiling (mma.sync fp16; A = x (K=1024), B = [Whi | Wlo] (K2=2048)).
// Modes 0,1 (Q,K): 2-term W. Modes 2,3 (V,O): 1-term (Whi only).
constexpr int TM  = 128;
constexpr int TN  = 128;
constexpr int K2  = 2 * EMB;          // 2048
constexpr int KC  = 64;               // fp16 per chunk = 128 B rows
constexpr int NPAIR = 16;             // A chunks
constexpr uint32_t GA_ST = 16384;     // A stage stride (16 KB)
constexpr uint32_t GB_OFF = 32768;    // B region base
constexpr uint32_t GB_ST = 32768;     // B pair-stage stride (2 tiles)
constexpr uint32_t GEMM_SMEM = 98304; // A 2x16K + B 2x32K

// Flash smem layout (bytes): Q 16K | KV 2 stages x 32K (2 sub-blocks each:
// K 8K + V 8K) | l 512B.  80.5 KB total -> 2 CTAs/SM.
constexpr uint32_t FQ   = 0;
constexpr uint32_t FKV  = 16384;
constexpr uint32_t FSTG = 32768;       // stage stride (2 sub-blocks)
constexpr uint32_t FSUB = 16384;       // sub-block stride (K 8K + V 8K)
constexpr uint32_t FLSM = 81920;
constexpr uint32_t FLASH_SMEM = 81920 + 512;

// ---------------------------------------------------------------------------
// Scratch (device globals -- no runtime allocation allowed)
// ---------------------------------------------------------------------------
__device__ float g_adapt[BATCH * EMB];

__device__ __half g_xh[(size_t)M_TOT * EMB];        // x rounded to fp16
__device__ __half g_ah[(size_t)M_TOT * EMB];        // attention out fp16
__device__ __half g_w2[4][(size_t)EMB * K2];        // transposed [n][whi | wlo]

__device__ __half g_qh[(size_t)BATCH * NH * SEQ * HD];  // [bh][s][d]
__device__ __half g_kh[(size_t)BATCH * NH * SEQ * HD];
__device__ __half g_vth[(size_t)BATCH * NH * HD * SEQ]; // [bh][d][s]

// ---------------------------------------------------------------------------
// Helpers
// ---------------------------------------------------------------------------
__device__ __forceinline__ uint32_t smem_u32(const void* p) {
    uint32_t a;
    asm("{ .reg .u64 t; cvta.to.shared.u64 t, %1; cvt.u32.u64 %0, t; }" : "=r"(a) : "l"(p));
    return a;
}
#define SWZ128(off) ((off) ^ (((off) >> 3) & 0x70))

__device__ __forceinline__ void cp16(uint32_t d, const void* g) {
    asm volatile("cp.async.cg.shared.global [%0], [%1], 16;" :: "r"(d), "l"(g));
}
__device__ __forceinline__ void ldm4(uint32_t* f, uint32_t addr) {
    asm volatile("ldmatrix.sync.aligned.m8n8.x4.shared.b16 {%0,%1,%2,%3}, [%4];"
        : "=r"(f[0]), "=r"(f[1]), "=r"(f[2]), "=r"(f[3]) : "r"(addr));
}
__device__ __forceinline__ void mma16816(float* c, const uint32_t* a, uint32_t b0, uint32_t b1) {
    asm volatile("mma.sync.aligned.m16n8k16.row.col.f32.f16.f16.f32 "
        "{%0,%1,%2,%3}, {%4,%5,%6,%7}, {%8,%9}, {%0,%1,%2,%3};"
        : "+f"(c[0]), "+f"(c[1]), "+f"(c[2]), "+f"(c[3])
        : "r"(a[0]), "r"(a[1]), "r"(a[2]), "r"(a[3]), "r"(b0), "r"(b1));
}
__device__ __forceinline__ float fast_ex2(float x) {
    float y; asm("ex2.approx.f32 %0, %1;" : "=f"(y) : "f"(x)); return y;
}
__device__ __forceinline__ uint32_t pack_h2(float a, float b) {
    __half2 t = __floats2half2_rn(a, b);
    uint32_t r;
    memcpy(&r, &t, 4);
    return r;
}

// ---------------------------------------------------------------------------
// Kernel: adapt
// ---------------------------------------------------------------------------
__global__ void adapt_kernel(const float* __restrict__ xi,
                             const float* __restrict__ ew1, const float* __restrict__ eb1,
                             const float* __restrict__ lng, const float* __restrict__ lnb,
                             const float* __restrict__ ew2, const float* __restrict__ eb2,
                             const float* __restrict__ gate)
{
    int b = threadIdx.x;
    if (b >= BATCH) return;
    float x[HD2];
    float xv = xi[b];
    float mu = 0.f;
#pragma unroll
    for (int i = 0; i < HD2; ++i) { x[i] = xv * ew1[i] + eb1[i]; mu += x[i]; }
    mu *= (1.0f / HD2);
    float var = 0.f;
#pragma unroll
    for (int i = 0; i < HD2; ++i) { float d = x[i] - mu; var += d * d; }
    var *= (1.0f / HD2);
    float rs = rsqrtf(var + 1e-5f);
#pragma unroll
    for (int i = 0; i < HD2; ++i) {
        float xn = (x[i] - mu) * rs * lng[i] + lnb[i];
        x[i] = 0.5f * xn * (1.f + erff(xn * 0.70710678118654752f));
    }
    float sg[NH];
#pragma unroll
    for (int h = 0; h < NH; ++h) sg[h] = 1.f / (1.f + expf(-gate[h]));
    for (int d = 0; d < HD; ++d) {
        float xe = eb2[d];
#pragma unroll
        for (int i = 0; i < HD2; ++i) xe += x[i] * ew2[i * HD + d];
#pragma unroll
        for (int h = 0; h < NH; ++h)
            g_adapt[b * EMB + h * HD + d] = 1.f + sg[h] * xe;
    }
}

// ---------------------------------------------------------------------------
// Kernel: fp32 -> fp16 (x4 vectorized)
// ---------------------------------------------------------------------------
__global__ void __launch_bounds__(256)
half_kernel(const float4* __restrict__ in, uint2* __restrict__ out, int n4)
{
    int i = blockIdx.x * 256 + threadIdx.x;
    if (i < n4) {
        float4 v = in[i];
        uint2 r;
        r.x = pack_h2(v.x, v.y);
        r.y = pack_h2(v.z, v.w);
        out[i] = r;
    }
}

// ---------------------------------------------------------------------------
// Kernel: all four W[K,N] fp32 -> transposed fp16 [N, 2048] = [hi | lo]
// ---------------------------------------------------------------------------
__global__ void __launch_bounds__(256)
wsplit2_all(const float* __restrict__ Wq, const float* __restrict__ Wk,
            const float* __restrict__ Wv, const float* __restrict__ Wo,
            __half* __restrict__ w2base)
{
    const float* W = (blockIdx.z == 0) ? Wq : (blockIdx.z == 1) ? Wk
                   : (blockIdx.z == 2) ? Wv : Wo;
    __half* out2 = w2base + (size_t)blockIdx.z * EMB * K2;

    __shared__ float t[32][33];
    int n0 = blockIdx.x * 32, k0 = blockIdx.y * 32;
    int tx = threadIdx.x, ty = threadIdx.y;   // (32, 8)
#pragma unroll
    for (int i = 0; i < 32; i += 8)
        t[ty + i][tx] = W[(size_t)(k0 + ty + i) * EMB + n0 + tx];
    __syncthreads();
#pragma unroll
    for (int i = 0; i < 32; i += 8) {
        float x = t[tx][ty + i];              // k=k0+tx, n=n0+ty+i
        __half h = __float2half_rn(x);
        __half l = __float2half_rn(x - __half2float(h));
        size_t base = (size_t)(n0 + ty + i) * K2 + k0 + tx;
        out2[base]       = h;
        out2[base + EMB] = l;
    }
}

// ---------------------------------------------------------------------------
// Kernel: mma.sync fp16 GEMM with paired K-chunks.
// Modes 0 (Q), 1 (K): 2-term W (hi+lo). Modes 2 (V), 3 (O): 1-term (hi only).
// ---------------------------------------------------------------------------
__global__ void __launch_bounds__(256)
gemm_mma(const __half* __restrict__ Ah, const __half* __restrict__ w2base,
         const float* __restrict__ bq, const float* __restrict__ bk,
         const float* __restrict__ bv, const float* __restrict__ bo,
         float* __restrict__ out, int mode_base)
{
    extern __shared__ __align__(1024) char smem[];
    const uint32_t sb = smem_u32(smem);
    const int tid  = threadIdx.x;
    const int lane = tid & 31;
    const int wid  = tid >> 5;
    const int wm   = wid >> 1;        // 0..3
    const int wn   = wid & 1;         // 0..1
    const int m0 = blockIdx.y * TM;
    const int n0 = blockIdx.x * TN;
    const int mode = mode_base + blockIdx.z;
    const bool two_term = (mode < 2);

    const float* bias = (mode == 0) ? bq : (mode == 1) ? bk : (mode == 2) ? bv : bo;
    const __half* Ab = Ah + (size_t)m0 * EMB;
    const __half* Bb = w2base + (size_t)mode * EMB * K2 + (size_t)n0 * K2;

    float c[2][8][4];
#pragma unroll
    for (int a = 0; a < 2; ++a)
#pragma unroll
        for (int b = 0; b < 8; ++b)
#pragma unroll
            for (int d = 0; d < 4; ++d) c[a][b][d] = 0.f;

#define PREPAIR(p)                                                                     \
    do {                                                                               \
        uint32_t sta = sb + ((p) & 1) * GA_ST;                                         \
        uint32_t stb = sb + GB_OFF + ((p) & 1) * GB_ST;                                \
        _Pragma("unroll")                                                              \
        for (int i = 0; i < 4; ++i) {                                                  \
            int idx = tid + i * 256;                                                   \
            int r = idx >> 3, u = idx & 7;                                             \
            uint32_t sw = SWZ128(r * 128 + u * 16);                                    \
            cp16(sta + sw, Ab + (size_t)r * EMB + (p) * KC + u * 8);                   \
            cp16(stb + sw, Bb + (size_t)r * K2 + (p) * KC + u * 8);                    \
            if (two_term)                                                              \
                cp16(stb + 16384 + sw, Bb + (size_t)r * K2 + EMB + (p) * KC + u * 8);  \
        }                                                                              \
        asm volatile("cp.async.commit_group;");                                        \
    } while (0)

    PREPAIR(0);
    asm volatile("cp.async.wait_group 0;");
    __syncthreads();

    for (int p = 0; p < NPAIR; ++p) {
        if (p + 1 < NPAIR) PREPAIR(p + 1);

        const uint32_t sta = sb + (p & 1) * GA_ST;
        const uint32_t stb = sb + GB_OFF + (p & 1) * GB_ST;
        const int rr = lane & 15;

#pragma unroll
        for (int ks = 0; ks < 4; ++ks) {
            const int uu = 2 * ks + (lane >> 4);
            uint32_t afr[2][4];
#pragma unroll
            for (int mt = 0; mt < 2; ++mt)
                ldm4(afr[mt], sta + SWZ128((wm * 32 + mt * 16 + rr) * 128 + uu * 16));
            // half 0 (Whi) always
            {
                uint32_t bfr[4][4];
#pragma unroll
                for (int ng = 0; ng < 4; ++ng)
                    ldm4(bfr[ng], stb + SWZ128((wn * 64 + ng * 16 + rr) * 128 + uu * 16));
#pragma unroll
                for (int mt = 0; mt < 2; ++mt)
#pragma unroll
                    for (int ng = 0; ng < 4; ++ng) {
                        mma16816(c[mt][ng * 2],     afr[mt], bfr[ng][0], bfr[ng][2]);
                        mma16816(c[mt][ng * 2 + 1], afr[mt], bfr[ng][1], bfr[ng][3]);
                    }
            }
            // half 1 (Wlo) only for Q/K
            if (two_term) {
                uint32_t bfr[4][4];
#pragma unroll
                for (int ng = 0; ng < 4; ++ng)
                    ldm4(bfr[ng], stb + 16384 +
                                  SWZ128((wn * 64 + ng * 16 + rr) * 128 + uu * 16));
#pragma unroll
                for (int mt = 0; mt < 2; ++mt)
#pragma unroll
                    for (int ng = 0; ng < 4; ++ng) {
                        mma16816(c[mt][ng * 2],     afr[mt], bfr[ng][0], bfr[ng][2]);
                        mma16816(c[mt][ng * 2 + 1], afr[mt], bfr[ng][1], bfr[ng][3]);
                    }
            }
        }

        if (p + 1 < NPAIR) {
            asm volatile("cp.async.wait_group 0;");
            __syncthreads();
        }
    }
#undef PREPAIR
    __syncthreads();

    // ---------------- epilogues ----------------
    if (mode == 2) {
        // V: stage transposed fp16 in smem, then coalesced store to [bh][d][s]
#pragma unroll
        for (int mt = 0; mt < 2; ++mt) {
            int mrow = wm * 32 + mt * 16 + (lane >> 2);
#pragma unroll
            for (int nt = 0; nt < 8; ++nt) {
                int nl = wn * 64 + nt * 8 + (lane & 3) * 2;
                float b0 = bias[n0 + nl], b1 = bias[n0 + nl + 1];
#pragma unroll
                for (int half = 0; half < 2; ++half) {
                    int ml = mrow + half * 8;
                    *(__half*)(smem + nl * 256 + ml * 2) =
                        __float2half_rn(c[mt][nt][half * 2] + b0);
                    *(__half*)(smem + (nl + 1) * 256 + ml * 2) =
                        __float2half_rn(c[mt][nt][half * 2 + 1] + b1);
                }
            }
        }
        __syncthreads();
        int bq2 = m0 >> 11, sq = m0 & 2047;
        int hbase = n0 >> 6;
        for (int cidx = tid; cidx < 2048; cidx += 256) {
            int nn = cidx >> 4, mc = cidx & 15;
            uint4 hv = *(uint4*)(smem + nn * 256 + mc * 16);
            size_t o = (((size_t)(bq2 * NH + hbase + (nn >> 6)) * HD + (nn & 63)) * SEQ
                        + sq + mc * 8);
            *(uint4*)&g_vth[o] = hv;
        }
        return;
    }

#pragma unroll
    for (int mt = 0; mt < 2; ++mt) {
        int row0 = wm * 32 + mt * 16 + (lane >> 2);
#pragma unroll
        for (int nt = 0; nt < 8; ++nt) {
            int n = n0 + wn * 64 + nt * 8 + (lane & 3) * 2;
            float b0 = bias[n], b1 = bias[n + 1];
#pragma unroll
            for (int half = 0; half < 2; ++half) {
                int m = m0 + row0 + half * 8;
                int b = m >> 11, s = m & 2047;
                float v0 = c[mt][nt][half * 2] + b0;
                float v1 = c[mt][nt][half * 2 + 1] + b1;
                if (mode == 3) {
                    *(float2*)&out[(size_t)m * EMB + n] = make_float2(v0, v1);
                } else {
                    const float sc0 = (mode == 0) ? 0.18033688f : 1.0f;  // 1.442695/8
                    v0 *= g_adapt[b * EMB + n] * sc0;
                    v1 *= g_adapt[b * EMB + n + 1] * sc0;
                    int h = n >> 6, d = n & 63;
                    size_t o = ((size_t)(b * NH + h) * SEQ + s) * HD + d;
                    uint32_t hp = pack_h2(v0, v1);
                    if (mode == 0) *(uint32_t*)&g_qh[o] = hp;
                    else           *(uint32_t*)&g_kh[o] = hp;
                }
            }
        }
    }
}

// ---------------------------------------------------------------------------
// Kernel: tensor-core flash attention (R16: 2 CTAs/SM, two 64-key sub-blocks
// per pipeline stage).
// ---------------------------------------------------------------------------
__global__ void __launch_bounds__(256, 2)
flash_tc()
{
    extern __shared__ __align__(1024) char smem[];
    const uint32_t sb = smem_u32(smem);
    const int tid = threadIdx.x, lane = tid & 31, wid = tid >> 5;
    const int wm = wid >> 1, wn = wid & 1;
    const int s0 = blockIdx.x * 128;
    const int h  = blockIdx.y, b = blockIdx.z;
    const int bh = b * NH + h;
    const int rr = lane & 15;
    const int NST = SEQ / 128;    // 16 stages, 2 sub-blocks each

    if (tid < 128) *(float*)(smem + FLSM + tid * 4) = 0.f;

    const __half* qh  = g_qh + ((size_t)bh * SEQ + s0) * HD;
    const __half* kh  = g_kh + (size_t)bh * SEQ * HD;
    const __half* vth = g_vth + (size_t)bh * HD * SEQ;

    // Q tile
#pragma unroll
    for (int i = 0; i < 4; ++i) {
        int idx = tid + i * 256;       // 0..1023
        int r = idx >> 3, u = idx & 7;
        cp16(sb + FQ + SWZ128(r * 128 + u * 16), qh + r * HD + u * 8);
    }
    asm volatile("cp.async.commit_group;");

// load stage st (key blocks 2*st and 2*st+1, 32 KB)
#define KVPRE(st)                                                                       \
    do {                                                                                \
        uint32_t base_ = sb + FKV + ((st) & 1) * FSTG;                                  \
        _Pragma("unroll")                                                               \
        for (int sub_ = 0; sub_ < 2; ++sub_) {                                          \
            int kb_ = (st) * 2 + sub_;                                                  \
            uint32_t stg_ = base_ + sub_ * FSUB;                                        \
            _Pragma("unroll")                                                           \
            for (int i = 0; i < 2; ++i) {                                               \
                int idx = tid + i * 256;     /* 0..511 */                               \
                int r = idx >> 3, u = idx & 7;                                          \
                uint32_t sw = SWZ128(r * 128 + u * 16);                                 \
                cp16(stg_ + sw,        kh + ((size_t)kb_ * 64 + r) * HD + u * 8);       \
                cp16(stg_ + 8192 + sw, vth + (size_t)r * SEQ + kb_ * 64 + u * 8);       \
            }                                                                           \
        }                                                                               \
        asm volatile("cp.async.commit_group;");                                         \
    } while (0)

    KVPRE(0);
    asm volatile("cp.async.wait_group 0;");
    __syncthreads();

    float oc[2][8][4];
#pragma unroll
    for (int a = 0; a < 2; ++a)
#pragma unroll
        for (int f = 0; f < 8; ++f)
#pragma unroll
            for (int d = 0; d < 4; ++d) oc[a][f][d] = 0.f;
    float l_part[4] = {0.f, 0.f, 0.f, 0.f};

#pragma unroll 1
    for (int st = 0; st < NST; ++st) {
        if (st + 1 < NST) KVPRE(st + 1);

#pragma unroll 1
        for (int sub = 0; sub < 2; ++sub) {
            const uint32_t stg = sb + FKV + (st & 1) * FSTG + sub * FSUB;

            // ---- S = Q K^T (fp16 single term) ----
            float sc[2][4][4];
#pragma unroll
            for (int a = 0; a < 2; ++a)
#pragma unroll
                for (int f = 0; f < 4; ++f)
#pragma unroll
                    for (int d = 0; d < 4; ++d) sc[a][f][d] = 0.f;

#pragma unroll
            for (int ks = 0; ks < 4; ++ks) {
                const int uu = 2 * ks + (lane >> 4);
                uint32_t aH[2][4], bH[2][4];
#pragma unroll
                for (int mt = 0; mt < 2; ++mt)
                    ldm4(aH[mt], sb + FQ + SWZ128((wm * 32 + mt * 16 + rr) * 128 + uu * 16));
#pragma unroll
                for (int ng = 0; ng < 2; ++ng)
                    ldm4(bH[ng], stg + SWZ128((wn * 32 + ng * 16 + rr) * 128 + uu * 16));
#pragma unroll
                for (int mt = 0; mt < 2; ++mt)
#pragma unroll
                    for (int ng = 0; ng < 2; ++ng) {
                        mma16816(sc[mt][ng * 2],     aH[mt], bH[ng][0], bH[ng][2]);
                        mma16816(sc[mt][ng * 2 + 1], aH[mt], bH[ng][1], bH[ng][3]);
                    }
            }

            // ---- p = 2^s; pack fp16 A-fragments in registers ----
            uint32_t pA[2][4], pB[2][4];
#pragma unroll
            for (int mt = 0; mt < 2; ++mt)
#pragma unroll
                for (int nf = 0; nf < 4; ++nf) {
                    float p0 = fast_ex2(sc[mt][nf][0]);
                    float p1 = fast_ex2(sc[mt][nf][1]);
                    float p2 = fast_ex2(sc[mt][nf][2]);
                    float p3 = fast_ex2(sc[mt][nf][3]);
                    l_part[mt * 2 + 0] += p0 + p1;
                    l_part[mt * 2 + 1] += p2 + p3;
                    pA[mt][nf] = pack_h2(p0, p1);
                    pB[mt][nf] = pack_h2(p2, p3);
                }

            // ---- O_partial += P V over this warp's 32 keys, all 64 d ----
#pragma unroll
            for (int ksp = 0; ksp < 2; ++ksp) {
                const int uu = 2 * (wn * 2 + ksp) + (lane >> 4);
                uint32_t bV[4][4];
#pragma unroll
                for (int g = 0; g < 4; ++g)
                    ldm4(bV[g], stg + 8192 + SWZ128((g * 16 + rr) * 128 + uu * 16));
#pragma unroll
                for (int mt = 0; mt < 2; ++mt) {
                    uint32_t aP[4] = {pA[mt][2 * ksp], pB[mt][2 * ksp],
                                      pA[mt][2 * ksp + 1], pB[mt][2 * ksp + 1]};
#pragma unroll
                    for (int g = 0; g < 4; ++g) {
                        mma16816(oc[mt][2 * g],     aP, bV[g][0], bV[g][2]);
                        mma16816(oc[mt][2 * g + 1], aP, bV[g][1], bV[g][3]);
                    }
                }
            }
        }

        // stage st fully consumed; wait for st+1 data and make write-safe
        if (st + 1 < NST) {
            asm volatile("cp.async.wait_group 0;");
            __syncthreads();
        }
    }
#undef KVPRE

    // ---- reduce l across the 4 lanes of each row-group ----
#pragma unroll
    for (int j = 0; j < 4; ++j) {
        l_part[j] += __shfl_xor_sync(0xFFFFFFFF, l_part[j], 1);
        l_part[j] += __shfl_xor_sync(0xFFFFFFFF, l_part[j], 2);
    }
    if ((lane & 3) == 0) {
#pragma unroll
        for (int mt = 0; mt < 2; ++mt)
#pragma unroll
            for (int half = 0; half < 2; ++half) {
                int r = wm * 32 + mt * 16 + (lane >> 2) + half * 8;
                atomicAdd((float*)(smem + FLSM + r * 4), l_part[mt * 2 + half]);
            }
    }
    __syncthreads();   // all PV done; Q area now dead -> O reduce buffer (32 KB)

    if (wn == 1) {
#pragma unroll
        for (int mt = 0; mt < 2; ++mt) {
            int row = wm * 32 + mt * 16 + (lane >> 2);
#pragma unroll
            for (int nf = 0; nf < 8; ++nf) {
                int col = nf * 8 + (lane & 3) * 2;
                *(float2*)(smem + (row * 64 + col) * 4) =
                    make_float2(oc[mt][nf][0], oc[mt][nf][1]);
                *(float2*)(smem + ((row + 8) * 64 + col) * 4) =
                    make_float2(oc[mt][nf][2], oc[mt][nf][3]);
            }
        }
    }
    __syncthreads();

    if (wn == 0) {
#pragma unroll
        for (int mt = 0; mt < 2; ++mt)
#pragma unroll
            for (int half = 0; half < 2; ++half) {
                int r = wm * 32 + mt * 16 + (lane >> 2) + half * 8;
                float inv = 1.f / *(float*)(smem + FLSM + r * 4);
                size_t mrow = (size_t)(b * SEQ + s0 + r) * EMB;
#pragma unroll
                for (int nf = 0; nf < 8; ++nf) {
                    int col = nf * 8 + (lane & 3) * 2;
                    float2 part = *(float2*)(smem + (r * 64 + col) * 4);
                    float v0 = (oc[mt][nf][half * 2]     + part.x) * inv;
                    float v1 = (oc[mt][nf][half * 2 + 1] + part.y) * inv;
                    *(uint32_t*)&g_ah[mrow + h * HD + col] = pack_h2(v0, v1);
                }
            }
    }
}

// ---------------------------------------------------------------------------
// Launch
// ---------------------------------------------------------------------------
extern "C" void kernel_launch(void* const* d_in, const int* in_sizes, int n_in,
                              void* d_out, int out_size)
{
    const float* query = (const float*)d_in[0];
    const float* xi    = (const float*)d_in[1];
    const float* Wq    = (const float*)d_in[2];
    const float* bq    = (const float*)d_in[3];
    const float* Wk    = (const float*)d_in[4];
    const float* bk    = (const float*)d_in[5];
    const float* Wv    = (const float*)d_in[6];
    const float* bv    = (const float*)d_in[7];
    const float* Wo    = (const float*)d_in[8];
    const float* bo    = (const float*)d_in[9];
    const float* ew1   = (const float*)d_in[10];
    const float* eb1   = (const float*)d_in[11];
    const float* lng   = (const float*)d_in[12];
    const float* lnb   = (const float*)d_in[13];
    const float* ew2   = (const float*)d_in[14];
    const float* eb2   = (const float*)d_in[15];
    const float* gate  = (const float*)d_in[16];
    float* out = (float*)d_out;

    // Idempotent, capture-safe, no static guard (harness rule).
    cudaFuncSetAttribute(gemm_mma, cudaFuncAttributeMaxDynamicSharedMemorySize, GEMM_SMEM);
    cudaFuncSetAttribute(flash_tc, cudaFuncAttributeMaxDynamicSharedMemorySize, FLASH_SMEM);

    int nX = M_TOT * EMB;
    __half *xh, *ah, *w2;
    cudaGetSymbolAddress((void**)&xh, g_xh);
    cudaGetSymbolAddress((void**)&ah, g_ah);
    cudaGetSymbolAddress((void**)&w2, g_w2);

    dim3 wgrid(EMB / 32, EMB / 32, 4);
    dim3 wblk(32, 8);
    dim3 gq(EMB / TN, M_TOT / TM, 3);    // QKV fused
    dim3 go(EMB / TN, M_TOT / TM, 1);    // O

    adapt_kernel<<<1, 32>>>(xi, ew1, eb1, lng, lnb, ew2, eb2, gate);
    half_kernel<<<nX / 1024, 256>>>((const float4*)query, (uint2*)xh, nX / 4);
    wsplit2_all<<<wgrid, wblk>>>(Wq, Wk, Wv, Wo, w2);
    gemm_mma<<<gq, 256, GEMM_SMEM>>>(xh, w2, bq, bk, bv, bo, out, 0);
    flash_tc<<<dim3(SEQ / 128, NH, BATCH), 256, FLASH_SMEM>>>();
    gemm_mma<<<go, 256, GEMM_SMEM>>>(ah, w2, bq, bk, bv, bo, out, 3);
}